// round 8
// baseline (speedup 1.0000x reference)
#include <cuda_runtime.h>
#include <cuda_bf16.h>
#include <cstdint>

// Problem constants
#define GRID_N   256
#define NB       1024
#define NH       32
#define NL       8
#define NS       8
#define BOUNDS_LO (-1.28f)
#define GRID_RES  (0.01f)
#define DIST_THR  (-0.01f)

// Fractional evict-last L2 policy (scalar-load compatible cache_hint form).
__device__ __forceinline__ uint64_t make_evict_last_policy() {
    uint64_t pol;
    asm("createpolicy.fractional.L2::evict_last.b64 %0, 1.0;" : "=l"(pol));
    return pol;
}

// SDF gather with L2 evict-last hint: keep the voxel grid resident in L2.
__device__ __forceinline__ float ldg_sdf(const float* p, uint64_t pol) {
    float v;
    asm volatile("ld.global.nc.L2::cache_hint.f32 %0, [%1], %2;"
                 : "=f"(v) : "l"(p), "l"(pol));
    return v;
}

// Voxel offset for one sphere, bit-identical to the R1/R3/R6 numerics
// (mul-then-add round-to-nearest, __fdiv_rn; rel_err 1.95e-4).
__device__ __forceinline__ int voxel_off(
    float r00, float r01, float r02, float r10, float r11, float r12,
    float r20, float r21, float r22, float px, float py, float pz,
    float cx, float cy, float cz)
{
    float x = __fadd_rn(__fadd_rn(__fadd_rn(__fmul_rn(r00, cx), __fmul_rn(r01, cy)), __fmul_rn(r02, cz)), px);
    float y = __fadd_rn(__fadd_rn(__fadd_rn(__fmul_rn(r10, cx), __fmul_rn(r11, cy)), __fmul_rn(r12, cz)), py);
    float z = __fadd_rn(__fadd_rn(__fadd_rn(__fmul_rn(r20, cx), __fmul_rn(r21, cy)), __fmul_rn(r22, cz)), pz);
    int ix = (int)floorf(__fdiv_rn(__fsub_rn(x, BOUNDS_LO), GRID_RES));
    int iy = (int)floorf(__fdiv_rn(__fsub_rn(y, BOUNDS_LO), GRID_RES));
    int iz = (int)floorf(__fdiv_rn(__fsub_rn(z, BOUNDS_LO), GRID_RES));
    ix = min(max(ix, 0), GRID_N - 1);
    iy = min(max(iy, 0), GRID_N - 1);
    iz = min(max(iz, 0), GRID_N - 1);
    return ((ix * GRID_N) + iy) * GRID_N + iz;
}

// Software-pipelined: each thread handles 2 (b,h,l) units (u and u+128, same
// link -> same sphere constants), 4 spheres each. 8 loads in flight per
// thread, issued as two 4-bursts separated by address math.
__global__ __launch_bounds__(256)
void voxel_collision_kernel(const float* __restrict__ link_pos,   // [B,H,L,3]
                            const float* __restrict__ link_rot,   // [B,H,L,3,3]
                            const float* __restrict__ sph_ctr,    // [L,S,3]
                            const float* __restrict__ sph_rad,    // [L,S]
                            const float* __restrict__ sdf,        // [256^3]
                            const float* __restrict__ weight,     // scalar
                            float* __restrict__ out)              // [B,H]
{
    // Block covers 256 (b,h,l) units.
    __shared__ float s_rot[256 * 9];       // 2304 floats
    __shared__ float s_pos[256 * 3];       // 768 floats
    __shared__ float s_ctr[NL * NS * 3];   // 192 floats
    __shared__ float s_rad[NL * NS];       // 64 floats

    // Coalesced, streaming staging of this block's pose data.
    {
        const float4* g4 = (const float4*)(link_rot + (size_t)blockIdx.x * 2304);
        float4* s4 = (float4*)s_rot;
        #pragma unroll
        for (int i = threadIdx.x; i < 576; i += 256) s4[i] = __ldcs(&g4[i]);

        const float4* p4 = (const float4*)(link_pos + (size_t)blockIdx.x * 768);
        float4* sp4 = (float4*)s_pos;
        if (threadIdx.x < 192) sp4[threadIdx.x] = __ldcs(&p4[threadIdx.x]);

        if (threadIdx.x < NL * NS * 3) s_ctr[threadIdx.x] = sph_ctr[threadIdx.x];
        if (threadIdx.x < NL * NS)     s_rad[threadIdx.x] = sph_rad[threadIdx.x];
    }
    __syncthreads();

    const int t  = threadIdx.x;
    const int uA = t >> 1;                   // unit A: 0..127
    const int uB = uA + 128;                 // unit B: 128..255 (same link id)
    const int l  = uA & (NL - 1);
    const int sb = (t & 1) * 4;              // sphere base: 0 or 4

    const uint64_t pol = make_evict_last_policy();

    // sphere constants shared by both units
    float cx[4], cy[4], cz[4], rad[4];
    #pragma unroll
    for (int s = 0; s < 4; s++) {
        const float* c = &s_ctr[(l * NS + sb + s) * 3];
        cx[s] = c[0]; cy[s] = c[1]; cz[s] = c[2];
        rad[s] = s_rad[l * NS + sb + s];
    }

    // ---- burst A: addresses + loads for unit A ----
    float svA[4];
    {
        const float a00 = s_rot[uA*9+0], a01 = s_rot[uA*9+1], a02 = s_rot[uA*9+2];
        const float a10 = s_rot[uA*9+3], a11 = s_rot[uA*9+4], a12 = s_rot[uA*9+5];
        const float a20 = s_rot[uA*9+6], a21 = s_rot[uA*9+7], a22 = s_rot[uA*9+8];
        const float ax = s_pos[uA*3+0], ay = s_pos[uA*3+1], az = s_pos[uA*3+2];
        #pragma unroll
        for (int s = 0; s < 4; s++) {
            int off = voxel_off(a00,a01,a02,a10,a11,a12,a20,a21,a22,
                                ax,ay,az, cx[s],cy[s],cz[s]);
            svA[s] = ldg_sdf(&sdf[off], pol);
        }
    }

    // ---- burst B: addresses + loads for unit B (A loads still in flight) ----
    float svB[4];
    {
        const float b00 = s_rot[uB*9+0], b01 = s_rot[uB*9+1], b02 = s_rot[uB*9+2];
        const float b10 = s_rot[uB*9+3], b11 = s_rot[uB*9+4], b12 = s_rot[uB*9+5];
        const float b20 = s_rot[uB*9+6], b21 = s_rot[uB*9+7], b22 = s_rot[uB*9+8];
        const float bx = s_pos[uB*3+0], by = s_pos[uB*3+1], bz = s_pos[uB*3+2];
        #pragma unroll
        for (int s = 0; s < 4; s++) {
            int off = voxel_off(b00,b01,b02,b10,b11,b12,b20,b21,b22,
                                bx,by,bz, cx[s],cy[s],cz[s]);
            svB[s] = ldg_sdf(&sdf[off], pol);
        }
    }

    const float w = __ldg(weight);           // off the critical path

    // ---- consume ----
    float mA = -1e30f, mB = -1e30f;
    #pragma unroll
    for (int s = 0; s < 4; s++) {
        mA = fmaxf(mA, rad[s] - svA[s]);
        mB = fmaxf(mB, rad[s] - svB[s]);
    }

    const unsigned mask = 0xFFFFFFFFu;
    // combine the two half-threads of each link (adjacent lanes)
    mA = fmaxf(mA, __shfl_xor_sync(mask, mA, 1));
    mB = fmaxf(mB, __shfl_xor_sync(mask, mB, 1));

    // threshold / clamp / normalize:  clip(m - 0.01, 0, 0.5) / 0.25
    float resA = fminf(fmaxf(mA + DIST_THR, 0.0f), 0.5f) * 4.0f;
    float resB = fminf(fmaxf(mB + DIST_THR, 0.0f), 0.5f) * 4.0f;

    // sum 8 links of one (b,h): lanes [16k..16k+15] reduce to lane 16k
    resA += __shfl_down_sync(mask, resA, 2);
    resB += __shfl_down_sync(mask, resB, 2);
    resA += __shfl_down_sync(mask, resA, 4);
    resB += __shfl_down_sync(mask, resB, 4);
    resA += __shfl_down_sync(mask, resA, 8);
    resB += __shfl_down_sync(mask, resB, 8);

    if ((t & 15) == 0) {
        const int base = blockIdx.x * 32;
        out[base + (t >> 4)]      = w * resA;   // units 0..127
        out[base + 16 + (t >> 4)] = w * resB;   // units 128..255
    }
}

extern "C" void kernel_launch(void* const* d_in, const int* in_sizes, int n_in,
                              void* d_out, int out_size)
{
    const float* link_pos = (const float*)d_in[0];  // [1024,32,8,3]
    const float* link_rot = (const float*)d_in[1];  // [1024,32,8,3,3]
    const float* sph_ctr  = (const float*)d_in[2];  // [8,8,3]
    const float* sph_rad  = (const float*)d_in[3];  // [8,8]
    const float* sdf      = (const float*)d_in[4];  // [256,256,256]
    const float* weight   = (const float*)d_in[5];  // scalar
    float* out = (float*)d_out;                     // [1024,32]

    // 1024 blocks x 256 threads; each thread covers 2 units x 4 spheres.
    voxel_collision_kernel<<<NB * NH * NL / 256, 256>>>(link_pos, link_rot,
                                                        sph_ctr, sph_rad, sdf,
                                                        weight, out);
}

// round 9
// speedup vs baseline: 1.0782x; 1.0782x over previous
#include <cuda_runtime.h>
#include <cuda_bf16.h>
#include <cstdint>

// Problem constants
#define GRID_N   256
#define NB       1024
#define NH       32
#define NL       8
#define NS       8
#define BOUNDS_LO (-1.28f)
#define GRID_RES  (0.01f)
#define DIST_THR  (-0.01f)

// Fractional evict-last L2 policy (scalar-load compatible cache_hint form).
__device__ __forceinline__ uint64_t make_evict_last_policy() {
    uint64_t pol;
    asm("createpolicy.fractional.L2::evict_last.b64 %0, 1.0;" : "=l"(pol));
    return pol;
}

// SDF gather with L2 evict-last hint: keep the voxel grid resident in L2.
__device__ __forceinline__ float ldg_sdf(const float* p, uint64_t pol) {
    float v;
    asm volatile("ld.global.nc.L2::cache_hint.f32 %0, [%1], %2;"
                 : "=f"(v) : "l"(p), "l"(pol));
    return v;
}

// R6 structure (best: 14.85us), one knob changed: 128-thread blocks,
// 16 blocks/SM. 2 threads per (b,h,l), 4 spheres each (MLP=4).
__global__ __launch_bounds__(128, 16)
void voxel_collision_kernel(const float* __restrict__ link_pos,   // [B,H,L,3]
                            const float* __restrict__ link_rot,   // [B,H,L,3,3]
                            const float* __restrict__ sph_ctr,    // [L,S,3]
                            const float* __restrict__ sph_rad,    // [L,S]
                            const float* __restrict__ sdf,        // [256^3]
                            const float* __restrict__ weight,     // scalar
                            float* __restrict__ out)              // [B,H]
{
    // Block covers 64 (b,h,l) units.
    __shared__ float s_rot[64 * 9];        // 576 floats
    __shared__ float s_pos[64 * 3];        // 192 floats
    __shared__ float s_ctr[NL * NS * 3];   // 192 floats
    __shared__ float s_rad[NL * NS];       // 64 floats

    // Coalesced, streaming staging of this block's pose data.
    {
        const float4* g4 = (const float4*)(link_rot + (size_t)blockIdx.x * 576);
        float4* s4 = (float4*)s_rot;
        #pragma unroll
        for (int i = threadIdx.x; i < 144; i += 128) s4[i] = __ldcs(&g4[i]);

        const float4* p4 = (const float4*)(link_pos + (size_t)blockIdx.x * 192);
        float4* sp4 = (float4*)s_pos;
        if (threadIdx.x < 48) sp4[threadIdx.x] = __ldcs(&p4[threadIdx.x]);

        if (threadIdx.x < NL * NS) {
            s_rad[threadIdx.x] = sph_rad[threadIdx.x];
            // 192 = 128 + 64: first 128 by all threads, last 64 by low half
            s_ctr[threadIdx.x] = sph_ctr[threadIdx.x];
            if (threadIdx.x < 64)
                s_ctr[128 + threadIdx.x] = sph_ctr[128 + threadIdx.x];
        } else {
            s_ctr[threadIdx.x] = sph_ctr[threadIdx.x];
        }
    }
    __syncthreads();

    const int u  = threadIdx.x >> 1;         // local (b,h,l) unit 0..63
    const int l  = u & (NL - 1);             // link id (block is 8-aligned)
    const int sb = (threadIdx.x & 1) * 4;    // sphere base: 0 or 4

    const float r00 = s_rot[u * 9 + 0], r01 = s_rot[u * 9 + 1], r02 = s_rot[u * 9 + 2];
    const float r10 = s_rot[u * 9 + 3], r11 = s_rot[u * 9 + 4], r12 = s_rot[u * 9 + 5];
    const float r20 = s_rot[u * 9 + 6], r21 = s_rot[u * 9 + 7], r22 = s_rot[u * 9 + 8];
    const float px = s_pos[u * 3 + 0], py = s_pos[u * 3 + 1], pz = s_pos[u * 3 + 2];

    const uint64_t pol = make_evict_last_policy();

    // 4 gather addresses computed back-to-back, then 4 independent loads.
    float sval[4];
    #pragma unroll
    for (int s = 0; s < 4; s++) {
        const float* c = &s_ctr[(l * NS + sb + s) * 3];
        const float cx = c[0], cy = c[1], cz = c[2];
        // mul-then-add, round-to-nearest, no FMA contraction (bit-identical to
        // the passing rounds' numerics; rel_err 1.95e-4).
        float x = __fadd_rn(__fadd_rn(__fadd_rn(__fmul_rn(r00, cx), __fmul_rn(r01, cy)), __fmul_rn(r02, cz)), px);
        float y = __fadd_rn(__fadd_rn(__fadd_rn(__fmul_rn(r10, cx), __fmul_rn(r11, cy)), __fmul_rn(r12, cz)), py);
        float z = __fadd_rn(__fadd_rn(__fadd_rn(__fmul_rn(r20, cx), __fmul_rn(r21, cy)), __fmul_rn(r22, cz)), pz);

        int ix = (int)floorf(__fdiv_rn(__fsub_rn(x, BOUNDS_LO), GRID_RES));
        int iy = (int)floorf(__fdiv_rn(__fsub_rn(y, BOUNDS_LO), GRID_RES));
        int iz = (int)floorf(__fdiv_rn(__fsub_rn(z, BOUNDS_LO), GRID_RES));
        ix = min(max(ix, 0), GRID_N - 1);
        iy = min(max(iy, 0), GRID_N - 1);
        iz = min(max(iz, 0), GRID_N - 1);
        sval[s] = ldg_sdf(&sdf[((ix * GRID_N) + iy) * GRID_N + iz], pol);
    }

    const float w = __ldg(weight);           // off the critical path

    // worst penetration over this thread's 4 spheres
    float m = -1e30f;
    #pragma unroll
    for (int s = 0; s < 4; s++)
        m = fmaxf(m, s_rad[l * NS + sb + s] - sval[s]);

    // combine the two half-threads of this link (adjacent lanes)
    const unsigned mask = 0xFFFFFFFFu;
    m = fmaxf(m, __shfl_xor_sync(mask, m, 1));

    // threshold / clamp / normalize:  clip(m - 0.01, 0, 0.5) / 0.25
    float res = m + DIST_THR;
    res = fminf(fmaxf(res, 0.0f), 0.5f) * 4.0f;

    // sum 8 links of one (b,h): lanes [16k .. 16k+15], one value per lane pair.
    res += __shfl_down_sync(mask, res, 2);
    res += __shfl_down_sync(mask, res, 4);
    res += __shfl_down_sync(mask, res, 8);

    if ((threadIdx.x & 15) == 0) {
        out[(blockIdx.x * 128 + threadIdx.x) >> 4] = w * res;
    }
}

extern "C" void kernel_launch(void* const* d_in, const int* in_sizes, int n_in,
                              void* d_out, int out_size)
{
    const float* link_pos = (const float*)d_in[0];  // [1024,32,8,3]
    const float* link_rot = (const float*)d_in[1];  // [1024,32,8,3,3]
    const float* sph_ctr  = (const float*)d_in[2];  // [8,8,3]
    const float* sph_rad  = (const float*)d_in[3];  // [8,8]
    const float* sdf      = (const float*)d_in[4];  // [256,256,256]
    const float* weight   = (const float*)d_in[5];  // scalar
    float* out = (float*)d_out;                     // [1024,32]

    const int total = NB * NH * NL * 2;             // 524288 threads
    voxel_collision_kernel<<<total / 128, 128>>>(link_pos, link_rot, sph_ctr,
                                                 sph_rad, sdf, weight, out);
}

// round 10
// speedup vs baseline: 1.1015x; 1.0216x over previous
#include <cuda_runtime.h>
#include <cuda_bf16.h>
#include <cstdint>

// Problem constants
#define GRID_N   256
#define NB       1024
#define NH       32
#define NL       8
#define NS       8
#define BOUNDS_LO (-1.28f)
#define GRID_RES  (0.01f)
#define DIST_THR  (-0.01f)

// 2 threads per (b,h,l): each handles 4 spheres (MLP=4), 524288 threads total.
// Gathers use ld.global.cg (L2-only, no L1 allocation): gather hit rate in L1
// is <1%, so skipping L1 line allocation removes tag churn from the replay
// path. Pose staging stays streaming (evict-first).
__global__ __launch_bounds__(256, 8)
void voxel_collision_kernel(const float* __restrict__ link_pos,   // [B,H,L,3]
                            const float* __restrict__ link_rot,   // [B,H,L,3,3]
                            const float* __restrict__ sph_ctr,    // [L,S,3]
                            const float* __restrict__ sph_rad,    // [L,S]
                            const float* __restrict__ sdf,        // [256^3]
                            const float* __restrict__ weight,     // scalar
                            float* __restrict__ out)              // [B,H]
{
    // Block covers 128 (b,h,l) units.
    __shared__ float s_rot[128 * 9];       // 1152 floats
    __shared__ float s_pos[128 * 3];       // 384 floats
    __shared__ float s_ctr[NL * NS * 3];   // 192 floats
    __shared__ float s_rad[NL * NS];       // 64 floats

    // Coalesced, streaming staging of this block's pose data.
    {
        const float4* g4 = (const float4*)(link_rot + (size_t)blockIdx.x * 1152);
        float4* s4 = (float4*)s_rot;
        #pragma unroll
        for (int i = threadIdx.x; i < 288; i += 256) s4[i] = __ldcs(&g4[i]);

        const float4* p4 = (const float4*)(link_pos + (size_t)blockIdx.x * 384);
        float4* sp4 = (float4*)s_pos;
        if (threadIdx.x < 96) sp4[threadIdx.x] = __ldcs(&p4[threadIdx.x]);

        if (threadIdx.x < NL * NS * 3) s_ctr[threadIdx.x] = sph_ctr[threadIdx.x];
        if (threadIdx.x < NL * NS)     s_rad[threadIdx.x] = sph_rad[threadIdx.x];
    }
    __syncthreads();

    const int u  = threadIdx.x >> 1;         // local (b,h,l) unit 0..127
    const int l  = u & (NL - 1);             // link id (block is 8-aligned)
    const int sb = (threadIdx.x & 1) * 4;    // sphere base: 0 or 4

    const float r00 = s_rot[u * 9 + 0], r01 = s_rot[u * 9 + 1], r02 = s_rot[u * 9 + 2];
    const float r10 = s_rot[u * 9 + 3], r11 = s_rot[u * 9 + 4], r12 = s_rot[u * 9 + 5];
    const float r20 = s_rot[u * 9 + 6], r21 = s_rot[u * 9 + 7], r22 = s_rot[u * 9 + 8];
    const float px = s_pos[u * 3 + 0], py = s_pos[u * 3 + 1], pz = s_pos[u * 3 + 2];

    // 4 gather addresses computed back-to-back, then 4 independent loads.
    float sval[4];
    #pragma unroll
    for (int s = 0; s < 4; s++) {
        const float* c = &s_ctr[(l * NS + sb + s) * 3];
        const float cx = c[0], cy = c[1], cz = c[2];
        // mul-then-add, round-to-nearest, no FMA contraction (bit-identical to
        // the passing rounds' numerics; rel_err 1.95e-4).
        float x = __fadd_rn(__fadd_rn(__fadd_rn(__fmul_rn(r00, cx), __fmul_rn(r01, cy)), __fmul_rn(r02, cz)), px);
        float y = __fadd_rn(__fadd_rn(__fadd_rn(__fmul_rn(r10, cx), __fmul_rn(r11, cy)), __fmul_rn(r12, cz)), py);
        float z = __fadd_rn(__fadd_rn(__fadd_rn(__fmul_rn(r20, cx), __fmul_rn(r21, cy)), __fmul_rn(r22, cz)), pz);

        int ix = (int)floorf(__fdiv_rn(__fsub_rn(x, BOUNDS_LO), GRID_RES));
        int iy = (int)floorf(__fdiv_rn(__fsub_rn(y, BOUNDS_LO), GRID_RES));
        int iz = (int)floorf(__fdiv_rn(__fsub_rn(z, BOUNDS_LO), GRID_RES));
        ix = min(max(ix, 0), GRID_N - 1);
        iy = min(max(iy, 0), GRID_N - 1);
        iz = min(max(iz, 0), GRID_N - 1);
        sval[s] = __ldcg(&sdf[((ix * GRID_N) + iy) * GRID_N + iz]);
    }

    const float w = __ldg(weight);           // off the critical path

    // worst penetration over this thread's 4 spheres
    float m = -1e30f;
    #pragma unroll
    for (int s = 0; s < 4; s++)
        m = fmaxf(m, s_rad[l * NS + sb + s] - sval[s]);

    // combine the two half-threads of this link (adjacent lanes)
    const unsigned mask = 0xFFFFFFFFu;
    m = fmaxf(m, __shfl_xor_sync(mask, m, 1));

    // threshold / clamp / normalize:  clip(m - 0.01, 0, 0.5) / 0.25
    float res = m + DIST_THR;
    res = fminf(fmaxf(res, 0.0f), 0.5f) * 4.0f;

    // sum 8 links of one (b,h): lanes [16k .. 16k+15], one value per lane pair.
    res += __shfl_down_sync(mask, res, 2);
    res += __shfl_down_sync(mask, res, 4);
    res += __shfl_down_sync(mask, res, 8);

    if ((threadIdx.x & 15) == 0) {
        out[(blockIdx.x * 256 + threadIdx.x) >> 4] = w * res;
    }
}

extern "C" void kernel_launch(void* const* d_in, const int* in_sizes, int n_in,
                              void* d_out, int out_size)
{
    const float* link_pos = (const float*)d_in[0];  // [1024,32,8,3]
    const float* link_rot = (const float*)d_in[1];  // [1024,32,8,3,3]
    const float* sph_ctr  = (const float*)d_in[2];  // [8,8,3]
    const float* sph_rad  = (const float*)d_in[3];  // [8,8]
    const float* sdf      = (const float*)d_in[4];  // [256,256,256]
    const float* weight   = (const float*)d_in[5];  // scalar
    float* out = (float*)d_out;                     // [1024,32]

    const int total = NB * NH * NL * 2;             // 524288 threads
    voxel_collision_kernel<<<total / 256, 256>>>(link_pos, link_rot, sph_ctr,
                                                 sph_rad, sdf, weight, out);
}